// round 16
// baseline (speedup 1.0000x reference)
#include <cuda_runtime.h>
#include <cuda_bf16.h>
#include <cuda_fp16.h>
#include <math.h>

// ---------------- constants ----------------
#define B_ 16
#define N_ 4096
#define C_ 256
#define H_ 4
#define D_ 64
#define M_ (B_ * N_)              // 65536
#define OUT_MAIN (M_ * C_)        // 16777216
#define OUT_S (B_ * H_ * D_ * D_) // 262144

typedef unsigned int u32;
typedef unsigned short u16;

// ---------------- device scratch ----------------
__device__ u16 g_wph[B_ * C_ * C_];            // W' = Sd@Wq per batch (fp16 rn)
__device__ u16 g_wk[C_ * C_];                  // Wk (bf16 rn, for gemm_k)
__device__ u16 g_wog[C_ * C_];                 // Wo*grms (fp16 rn)
__device__ float g_y[M_ * C_];
__device__ float g_beta[B_ * H_ * N_];
__device__ float g_ssp[M_ * 2];
__device__ float g_invrms[M_];
__device__ float g_mkp[512 * 256], g_mbkp[512 * 256];   // per-mtile k partials
__device__ float g_xbp[1024 * H_ * C_];                  // per-64row beta*x partials
__device__ float g_werr[64 * 64], g_wkey[64 * 64];

// ---------------- helpers ----------------
__device__ __forceinline__ u32 smem_u32(const void* p) {
    u32 a;
    asm("{ .reg .u64 t; cvta.to.shared.u64 t, %1; cvt.u32.u64 %0, t; }" : "=r"(a) : "l"(p));
    return a;
}
__device__ __forceinline__ void ldmx4(u32* r, u32 addr) {
    asm volatile("ldmatrix.sync.aligned.m8n8.x4.shared.b16 {%0,%1,%2,%3}, [%4];"
                 : "=r"(r[0]), "=r"(r[1]), "=r"(r[2]), "=r"(r[3]) : "r"(addr));
}
__device__ __forceinline__ void mma_bf16(float* d, const u32* a, u32 b0, u32 b1) {
    asm volatile("mma.sync.aligned.m16n8k16.row.col.f32.bf16.bf16.f32 "
                 "{%0,%1,%2,%3}, {%4,%5,%6,%7}, {%8,%9}, {%0,%1,%2,%3};"
                 : "+f"(d[0]), "+f"(d[1]), "+f"(d[2]), "+f"(d[3])
                 : "r"(a[0]), "r"(a[1]), "r"(a[2]), "r"(a[3]), "r"(b0), "r"(b1));
}
__device__ __forceinline__ void mma_f16(float* d, const u32* a, u32 b0, u32 b1) {
    asm volatile("mma.sync.aligned.m16n8k16.row.col.f32.f16.f16.f32 "
                 "{%0,%1,%2,%3}, {%4,%5,%6,%7}, {%8,%9}, {%0,%1,%2,%3};"
                 : "+f"(d[0]), "+f"(d[1]), "+f"(d[2]), "+f"(d[3])
                 : "r"(a[0]), "r"(a[1]), "r"(a[2]), "r"(a[3]), "r"(b0), "r"(b1));
}
// fp16 RN pair: low = f0, high = f1
__device__ __forceinline__ u32 f16pair(float f0, float f1) {
    u32 r;
    asm("cvt.rn.f16x2.f32 %0, %1, %2;" : "=r"(r) : "f"(f1), "f"(f0));
    return r;
}
// fp16 split: h = rn16(f), l = rn16(f - h)  (a = h + l to ~2^-24)
__device__ __forceinline__ void split2h(float f0, float f1, u32& h01, u32& l01) {
    h01 = f16pair(f0, f1);
    __half2 hp = *reinterpret_cast<__half2*>(&h01);
    float2 bk = __half22float2(hp);
    l01 = f16pair(f0 - bk.x, f1 - bk.y);
}
// RN bf16 pair pack: low half = f0, high half = f1
__device__ __forceinline__ u32 bf16pair(float f0, float f1) {
    u32 r;
    asm("cvt.rn.bf16x2.f32 %0, %1, %2;" : "=r"(r) : "f"(f1), "f"(f0));
    return r;
}
__device__ __forceinline__ float eluf(float v) {
    return (v > 0.f) ? (v + 1.f) : expf(v);
}
#define CP_ASYNC16(dst, src) \
    asm volatile("cp.async.cg.shared.global [%0], [%1], 16;" :: "r"(dst), "l"(src))
#define CP_COMMIT() asm volatile("cp.async.commit_group;")
#define CP_WAIT0()  asm volatile("cp.async.wait_group 0;" ::: "memory")

// ---------------- K0: Wk -> bf16, Wo*grms -> fp16 ----------------
__global__ void __launch_bounds__(256) convw_kernel(
    const float* __restrict__ Wk, const float* __restrict__ Wo,
    const float* __restrict__ grms)
{
    int gid = blockIdx.x * 256 + threadIdx.x;   // < 131072
    int sel = gid >> 16, idx = gid & 65535;
    if (sel) {
        float v = Wo[idx] * grms[idx & 255];
        g_wog[idx] = __half_as_ushort(__float2half_rn(v));
    } else {
        g_wk[idx] = __bfloat16_as_ushort(__float2bfloat16(Wk[idx]));
    }
}

// ---------------- K0b: beta = sigmoid(x @ Wb^T), warp per row ----------------
__global__ void __launch_bounds__(256)
beta_kernel(const float* __restrict__ x, const float* __restrict__ Wb)
{
    int warp = (blockIdx.x * 256 + threadIdx.x) >> 5;
    int lane = threadIdx.x & 31;
    int m = warp;
    float a0 = 0.f, a1 = 0.f, a2 = 0.f, a3 = 0.f;
#pragma unroll
    for (int cc = 0; cc < 8; cc++) {
        int c = cc * 32 + lane;
        float xv = x[(size_t)m * C_ + c];
        a0 += xv * Wb[c];
        a1 += xv * Wb[256 + c];
        a2 += xv * Wb[512 + c];
        a3 += xv * Wb[768 + c];
    }
#pragma unroll
    for (int o = 16; o; o >>= 1) {
        a0 += __shfl_down_sync(0xffffffffu, a0, o);
        a1 += __shfl_down_sync(0xffffffffu, a1, o);
        a2 += __shfl_down_sync(0xffffffffu, a2, o);
        a3 += __shfl_down_sync(0xffffffffu, a3, o);
    }
    if (lane == 0) {
        int bb = m >> 12, n = m & (N_ - 1);
        g_beta[(bb * H_ + 0) * N_ + n] = 1.f / (1.f + expf(-a0));
        g_beta[(bb * H_ + 1) * N_ + n] = 1.f / (1.f + expf(-a1));
        g_beta[(bb * H_ + 2) * N_ + n] = 1.f / (1.f + expf(-a2));
        g_beta[(bb * H_ + 3) * N_ + n] = 1.f / (1.f + expf(-a3));
    }
}

// ---------------- K1: W'[b] = (0.95*S[b,h]) @ Wq_h -> fp16 rn ----------------
__global__ void __launch_bounds__(256)
wprime_kernel(const float* __restrict__ S, const float* __restrict__ Wq)
{
    extern __shared__ float sm[];        // sSdT[4096] + sWq[64*256] = 80KB
    float* sSdT = sm;
    float* sWq = sm + 4096;
    int bh = blockIdx.x, b = bh >> 2, h = bh & 3, tid = threadIdx.x;
    for (int t = tid; t < 4096; t += 256) {
        int i = t >> 6, j = t & 63;
        sSdT[j * 64 + i] = S[(size_t)bh * 4096 + t] * 0.95f;
    }
    for (int t = tid; t < 64 * 256; t += 256)
        sWq[t] = Wq[(size_t)(h * 64 + (t >> 8)) * 256 + (t & 255)];
    __syncthreads();
    int i = tid & 63, stripe = tid >> 6;
#pragma unroll 1
    for (int cc = 0; cc < 64; cc++) {
        int c = stripe * 64 + cc;
        float acc = 0.f;
#pragma unroll
        for (int j = 0; j < 64; j++)
            acc += sSdT[j * 64 + i] * sWq[j * 256 + c];
        size_t o = (size_t)b * 65536 + (size_t)(h * 64 + i) * 256 + c;
        g_wph[o] = __half_as_ushort(__float2half_rn(acc));
    }
}

// ============ pipelined GEMM bodies (K=32 chunks, double buffered) ============

// ---------------- K2/K6: projection GEMM, 2-pass fp16 (A split, B rn), 128x128 ----------------
// grid (2, rows/128) per M-chunk; mbase selects the chunk.
__global__ void __launch_bounds__(256, 2)
gemm_proj_kernel(int task, int mbase, const float* __restrict__ Xfp, float* __restrict__ fout)
{
    extern __shared__ char smem[];
    __shared__ float sm_ss[128][2];
    const u32 sb = smem_u32(smem);
    const int tid = threadIdx.x, wid = tid >> 5, lane = tid & 31;
    const int m0 = mbase + blockIdx.y * 128;
    const int n0 = (int)blockIdx.x * 128;

    const float* Afp = (task == 0) ? Xfp : g_y;
    const u16* Bp = (task == 0) ? (g_wph + (size_t)(m0 >> 12) * 65536) : g_wog;

    const int wm = wid & 3, wn = wid >> 2;
    const int rA = (lane & 7) + ((lane >> 3) & 1) * 8, cAx = (lane >> 4) & 1;
    const int rB = (lane & 7) + ((lane >> 4) & 1) * 8, cBx = (lane >> 3) & 1;

    float acc[2][8][4];
#pragma unroll
    for (int i = 0; i < 2; i++)
#pragma unroll
        for (int j = 0; j < 8; j++)
#pragma unroll
            for (int t = 0; t < 4; t++) acc[i][j][t] = 0.f;

    const int lr = tid >> 1, q = tid & 1;
    const size_t arow = (size_t)(m0 + lr) * C_ + q * 16;
    const size_t brow = (size_t)(n0 + lr) * C_;
    float fr[16];

#define LD_A(c) do { \
    const float4* _p = (const float4*)(Afp + arow + (c) * 32); \
    *(float4*)(fr)      = _p[0]; *(float4*)(fr + 4)  = _p[1]; \
    *(float4*)(fr + 8)  = _p[2]; *(float4*)(fr + 12) = _p[3]; \
} while (0)

#define LD_B(c, ob) do { \
    _Pragma("unroll") \
    for (int _i = 0; _i < 2; _i++) { \
        int _cg = q * 2 + _i; \
        u32 _row = (ob) + (u32)lr * 128; \
        CP_ASYNC16(sb + _row + (u32)((_cg ^ (lr & 7)) << 4), \
                   (const void*)(Bp + brow + (c) * 32 + _cg * 8)); \
    } \
    CP_COMMIT(); \
} while (0)

#define ST_A(c, oa) do { \
    u32 _hv[8], _lv[8]; \
    _Pragma("unroll") \
    for (int _t = 0; _t < 8; _t++) split2h(fr[2 * _t], fr[2 * _t + 1], _hv[_t], _lv[_t]); \
    u32 _base = (oa) + (u32)lr * 128; \
    int _c0 = q * 2, _c1 = q * 2 + 1; \
    *(uint4*)(smem + _base + ((_c0 ^ (lr & 7)) << 4))       = make_uint4(_hv[0], _hv[1], _hv[2], _hv[3]); \
    *(uint4*)(smem + _base + ((_c1 ^ (lr & 7)) << 4))       = make_uint4(_hv[4], _hv[5], _hv[6], _hv[7]); \
    *(uint4*)(smem + _base + (((_c0 + 4) ^ (lr & 7)) << 4)) = make_uint4(_lv[0], _lv[1], _lv[2], _lv[3]); \
    *(uint4*)(smem + _base + (((_c1 + 4) ^ (lr & 7)) << 4)) = make_uint4(_lv[4], _lv[5], _lv[6], _lv[7]); \
} while (0)

#define MMA_CHUNK(s) do { \
    u32 _oa = (u32)(s) * 32768, _obm = _oa + 16384; \
    _Pragma("unroll") \
    for (int ks = 0; ks < 2; ks++) { \
        u32 ah[2][4], al[2][4]; \
        _Pragma("unroll") \
        for (int ms = 0; ms < 2; ms++) { \
            int r = wm * 32 + ms * 16 + rA; \
            u32 rowb = _oa + (u32)r * 128; \
            ldmx4(ah[ms], sb + rowb + (u32)((((2 * ks + cAx)) ^ (r & 7)) << 4)); \
            ldmx4(al[ms], sb + rowb + (u32)((((2 * ks + cAx) + 4) ^ (r & 7)) << 4)); \
        } \
        _Pragma("unroll") \
        for (int nh = 0; nh < 4; nh++) { \
            int n = wn * 64 + nh * 16 + rB; \
            u32 rowbB = _obm + (u32)n * 128; \
            u32 bhf[4]; \
            ldmx4(bhf, sb + rowbB + (u32)((((2 * ks + cBx)) ^ (n & 7)) << 4)); \
            mma_f16(acc[0][nh * 2],     ah[0], bhf[0], bhf[1]); \
            mma_f16(acc[1][nh * 2],     ah[1], bhf[0], bhf[1]); \
            mma_f16(acc[0][nh * 2 + 1], ah[0], bhf[2], bhf[3]); \
            mma_f16(acc[1][nh * 2 + 1], ah[1], bhf[2], bhf[3]); \
            mma_f16(acc[0][nh * 2],     al[0], bhf[0], bhf[1]); \
            mma_f16(acc[1][nh * 2],     al[1], bhf[0], bhf[1]); \
            mma_f16(acc[0][nh * 2 + 1], al[0], bhf[2], bhf[3]); \
            mma_f16(acc[1][nh * 2 + 1], al[1], bhf[2], bhf[3]); \
        } \
    } \
} while (0)

    LD_A(0);
    LD_B(0, 16384u);
    ST_A(0, 0u);
    CP_WAIT0();
    __syncthreads();

#pragma unroll
    for (int c = 0; c < 8; c++) {
        if (c < 7) { LD_A(c + 1); LD_B(c + 1, (u32)(((c + 1) & 1) * 32768 + 16384)); }
        MMA_CHUNK(c & 1);
        if (c < 7) {
            ST_A(c + 1, (u32)(((c + 1) & 1) * 32768));
            CP_WAIT0();
            __syncthreads();
        }
    }

    // ---- epilogue ----
    const int qrow = lane >> 2, qcol = (lane & 3) * 2;
    if (task == 0) {
#pragma unroll
        for (int mm = 0; mm < 2; mm++) {
            size_t r_lo = (size_t)(m0 + wm * 32 + mm * 16 + qrow);
            size_t r_hi = r_lo + 8;
            float ssl = 0.f, ssh = 0.f;
#pragma unroll
            for (int nf = 0; nf < 8; nf++) {
                int cof = n0 + wn * 64 + nf * 8 + qcol;
                *(float2*)(g_y + r_lo * C_ + cof) = make_float2(acc[mm][nf][0], acc[mm][nf][1]);
                *(float2*)(g_y + r_hi * C_ + cof) = make_float2(acc[mm][nf][2], acc[mm][nf][3]);
                ssl += acc[mm][nf][0] * acc[mm][nf][0] + acc[mm][nf][1] * acc[mm][nf][1];
                ssh += acc[mm][nf][2] * acc[mm][nf][2] + acc[mm][nf][3] * acc[mm][nf][3];
            }
            ssl += __shfl_xor_sync(0xffffffffu, ssl, 1);
            ssl += __shfl_xor_sync(0xffffffffu, ssl, 2);
            ssh += __shfl_xor_sync(0xffffffffu, ssh, 1);
            ssh += __shfl_xor_sync(0xffffffffu, ssh, 2);
            if ((lane & 3) == 0) {
                sm_ss[wm * 32 + mm * 16 + qrow][wn]     = ssl;
                sm_ss[wm * 32 + mm * 16 + qrow + 8][wn] = ssh;
            }
        }
        __syncthreads();
        if (tid < 128)
            g_ssp[(size_t)(m0 + tid) * 2 + (n0 >> 7)] = sm_ss[tid][0] + sm_ss[tid][1];
    } else {
#pragma unroll
        for (int mm = 0; mm < 2; mm++) {
            size_t r_lo = (size_t)(m0 + wm * 32 + mm * 16 + qrow);
            size_t r_hi = r_lo + 8;
            float irm_lo = g_invrms[r_lo];
            float irm_hi = g_invrms[r_hi];
#pragma unroll
            for (int nf = 0; nf < 8; nf++) {
                int cof = n0 + wn * 64 + nf * 8 + qcol;
                *(float2*)(fout + r_lo * C_ + cof) =
                    make_float2(acc[mm][nf][0] * irm_lo, acc[mm][nf][1] * irm_lo);
                *(float2*)(fout + r_hi * C_ + cof) =
                    make_float2(acc[mm][nf][2] * irm_hi, acc[mm][nf][3] * irm_hi);
            }
        }
    }
#undef LD_A
#undef LD_B
#undef ST_A
#undef MMA_CHUNK
}

// ---------------- K4: k GEMM, single-pass bf16 (k only feeds means) ----------------
__global__ void __launch_bounds__(256, 2)
gemm_k_kernel(const float* __restrict__ Xfp)
{
    extern __shared__ char smem[];
    const u32 sb = smem_u32(smem);
    const int tid = threadIdx.x, wid = tid >> 5, lane = tid & 31;
    const int m0 = blockIdx.y * 128;
    const int n0 = (int)blockIdx.x * 128;
    const u16* Bp = g_wk;

    const int wm = wid & 3, wn = wid >> 2;
    const int rA = (lane & 7) + ((lane >> 3) & 1) * 8, cAx = (lane >> 4) & 1;
    const int rB = (lane & 7) + ((lane >> 4) & 1) * 8, cBx = (lane >> 3) & 1;

    float acc[2][8][4];
#pragma unroll
    for (int i = 0; i < 2; i++)
#pragma unroll
        for (int j = 0; j < 8; j++)
#pragma unroll
            for (int t = 0; t < 4; t++) acc[i][j][t] = 0.f;

    const int lr = tid >> 1, q = tid & 1;
    const size_t arow = (size_t)(m0 + lr) * C_ + q * 16;
    const size_t brow = (size_t)(n0 + lr) * C_;
    float fr[16];

#define LD_A(c) do { \
    const float4* _p = (const float4*)(Xfp + arow + (c) * 32); \
    *(float4*)(fr)      = _p[0]; *(float4*)(fr + 4)  = _p[1]; \
    *(float4*)(fr + 8)  = _p[2]; *(float4*)(fr + 12) = _p[3]; \
} while (0)

#define LD_B(c, ob) do { \
    _Pragma("unroll") \
    for (int _i = 0; _i < 2; _i++) { \
        int _cg = q * 2 + _i; \
        u32 _row = (ob) + (u32)lr * 128; \
        CP_ASYNC16(sb + _row + (u32)((_cg ^ (lr & 7)) << 4), \
                   (const void*)(Bp + brow + (c) * 32 + _cg * 8)); \
    } \
    CP_COMMIT(); \
} while (0)

#define ST_A(c, oa) do { \
    u32 _hv[8]; \
    _Pragma("unroll") \
    for (int _t = 0; _t < 8; _t++) _hv[_t] = bf16pair(fr[2 * _t], fr[2 * _t + 1]); \
    u32 _base = (oa) + (u32)lr * 128; \
    int _c0 = q * 2, _c1 = q * 2 + 1; \
    *(uint4*)(smem + _base + ((_c0 ^ (lr & 7)) << 4)) = make_uint4(_hv[0], _hv[1], _hv[2], _hv[3]); \
    *(uint4*)(smem + _base + ((_c1 ^ (lr & 7)) << 4)) = make_uint4(_hv[4], _hv[5], _hv[6], _hv[7]); \
} while (0)

#define MMA_CHUNK(s) do { \
    u32 _oa = (u32)(s) * 32768, _obm = _oa + 16384; \
    _Pragma("unroll") \
    for (int ks = 0; ks < 2; ks++) { \
        u32 ah[2][4]; \
        _Pragma("unroll") \
        for (int ms = 0; ms < 2; ms++) { \
            int r = wm * 32 + ms * 16 + rA; \
            u32 rowb = _oa + (u32)r * 128; \
            ldmx4(ah[ms], sb + rowb + (u32)((((2 * ks + cAx)) ^ (r & 7)) << 4)); \
        } \
        _Pragma("unroll") \
        for (int nh = 0; nh < 4; nh++) { \
            int n = wn * 64 + nh * 16 + rB; \
            u32 rowbB = _obm + (u32)n * 128; \
            u32 bhf[4]; \
            ldmx4(bhf, sb + rowbB + (u32)((((2 * ks + cBx)) ^ (n & 7)) << 4)); \
            mma_bf16(acc[0][nh * 2],     ah[0], bhf[0], bhf[1]); \
            mma_bf16(acc[1][nh * 2],     ah[1], bhf[0], bhf[1]); \
            mma_bf16(acc[0][nh * 2 + 1], ah[0], bhf[2], bhf[3]); \
            mma_bf16(acc[1][nh * 2 + 1], ah[1], bhf[2], bhf[3]); \
        } \
    } \
} while (0)

    LD_A(0);
    LD_B(0, 16384u);
    ST_A(0, 0u);
    CP_WAIT0();
    __syncthreads();

#pragma unroll
    for (int c = 0; c < 8; c++) {
        if (c < 7) { LD_A(c + 1); LD_B(c + 1, (u32)(((c + 1) & 1) * 32768 + 16384)); }
        MMA_CHUNK(c & 1);
        if (c < 7) {
            ST_A(c + 1, (u32)(((c + 1) & 1) * 32768));
            CP_WAIT0();
            __syncthreads();
        }
    }

    // ---- epilogue: elu+1, per-head L2 norm, reduce mk & beta-weighted mbk ----
    const int qrow = lane >> 2, qcol = (lane & 3) * 2;
    const int head = (n0 >> 6) + wn;
    const int bhh = (m0 >> 12) * H_ + head;
    float mk0[8], mk1[8], mbk0[8], mbk1[8];
#pragma unroll
    for (int nf = 0; nf < 8; nf++) { mk0[nf] = mk1[nf] = mbk0[nf] = mbk1[nf] = 0.f; }

#pragma unroll
    for (int mm = 0; mm < 2; mm++) {
        float ssl = 0.f, ssh = 0.f;
#pragma unroll
        for (int nf = 0; nf < 8; nf++) {
            float e0 = eluf(acc[mm][nf][0]); acc[mm][nf][0] = e0; ssl += e0 * e0;
            float e1 = eluf(acc[mm][nf][1]); acc[mm][nf][1] = e1; ssl += e1 * e1;
            float e2 = eluf(acc[mm][nf][2]); acc[mm][nf][2] = e2; ssh += e2 * e2;
            float e3 = eluf(acc[mm][nf][3]); acc[mm][nf][3] = e3; ssh += e3 * e3;
        }
        ssl += __shfl_xor_sync(0xffffffffu, ssl, 1);
        ssl += __shfl_xor_sync(0xffffffffu, ssl, 2);
        ssh += __shfl_xor_sync(0xffffffffu, ssh, 1);
        ssh += __shfl_xor_sync(0xffffffffu, ssh, 2);
        float invl = 1.f / (sqrtf(ssl) + 1e-6f);
        float invh = 1.f / (sqrtf(ssh) + 1e-6f);
        int nrow = (m0 & (N_ - 1)) + wm * 32 + mm * 16 + qrow;
        float b_lo = g_beta[bhh * N_ + nrow];
        float b_hi = g_beta[bhh * N_ + nrow + 8];
#pragma unroll
        for (int nf = 0; nf < 8; nf++) {
            float v0 = acc[mm][nf][0] * invl, v1 = acc[mm][nf][1] * invl;
            float v2 = acc[mm][nf][2] * invh, v3 = acc[mm][nf][3] * invh;
            mk0[nf]  += v0 + v2;
            mk1[nf]  += v1 + v3;
            mbk0[nf] += b_lo * v0 + b_hi * v2;
            mbk1[nf] += b_lo * v1 + b_hi * v3;
        }
    }
#pragma unroll
    for (int o = 4; o <= 16; o <<= 1) {
#pragma unroll
        for (int nf = 0; nf < 8; nf++) {
            mk0[nf]  += __shfl_xor_sync(0xffffffffu, mk0[nf], o);
            mk1[nf]  += __shfl_xor_sync(0xffffffffu, mk1[nf], o);
            mbk0[nf] += __shfl_xor_sync(0xffffffffu, mbk0[nf], o);
            mbk1[nf] += __shfl_xor_sync(0xffffffffu, mbk1[nf], o);
        }
    }
    __syncthreads();
    float* red = (float*)smem;   // reuse staging smem: [0,512) mk, [512,1024) mbk
    if (lane < 4) {
#pragma unroll
        for (int nf = 0; nf < 8; nf++) {
            red[wid * 64 + nf * 8 + lane * 2]           = mk0[nf];
            red[wid * 64 + nf * 8 + lane * 2 + 1]       = mk1[nf];
            red[512 + wid * 64 + nf * 8 + lane * 2]     = mbk0[nf];
            red[512 + wid * 64 + nf * 8 + lane * 2 + 1] = mbk1[nf];
        }
    }
    __syncthreads();
    if (tid < 128) {
        int hh = tid >> 6, col = tid & 63;
        float s = red[(hh * 4 + 0) * 64 + col] + red[(hh * 4 + 1) * 64 + col]
                + red[(hh * 4 + 2) * 64 + col] + red[(hh * 4 + 3) * 64 + col];
        g_mkp[(size_t)blockIdx.y * 256 + n0 + hh * 64 + col] = s;
    } else {
        int t2 = tid - 128, hh = t2 >> 6, col = t2 & 63;
        float s = red[512 + (hh * 4 + 0) * 64 + col] + red[512 + (hh * 4 + 1) * 64 + col]
                + red[512 + (hh * 4 + 2) * 64 + col] + red[512 + (hh * 4 + 3) * 64 + col];
        g_mbkp[(size_t)blockIdx.y * 256 + n0 + hh * 64 + col] = s;
    }
#undef LD_A
#undef LD_B
#undef ST_A
#undef MMA_CHUNK
}

// ---------------- K3: xbar partials = sum_n beta*x over 64-row chunks ----------------
__global__ void __launch_bounds__(256)
xbar_kernel(const float* __restrict__ x)
{
    __shared__ float sbeta[64][4];
    int blk = blockIdx.x, m0 = blk * 64, tid = threadIdx.x;
    {
        int r = tid >> 2, h = tid & 3;
        int m = m0 + r, b = m >> 12, n = m & (N_ - 1);
        sbeta[r][h] = g_beta[(b * H_ + h) * N_ + n];
    }
    __syncthreads();
    float a0 = 0.f, a1 = 0.f, a2 = 0.f, a3 = 0.f;
    for (int r = 0; r < 64; r++) {
        float xv = x[(size_t)(m0 + r) * C_ + tid];
        a0 += xv * sbeta[r][0];
        a1 += xv * sbeta[r][1];
        a2 += xv * sbeta[r][2];
        a3 += xv * sbeta[r][3];
    }
    g_xbp[((size_t)blk * 4 + 0) * 256 + tid] = a0;
    g_xbp[((size_t)blk * 4 + 1) * 256 + tid] = a1;
    g_xbp[((size_t)blk * 4 + 2) * 256 + tid] = a2;
    g_xbp[((size_t)blk * 4 + 3) * 256 + tid] = a3;
}

// ---------------- K5a: invrms (per M-chunk) ----------------
__global__ void __launch_bounds__(256)
invrms_kernel(int mbase)
{
    int m = mbase + blockIdx.x * 256 + threadIdx.x;
    float s = g_ssp[(size_t)m * 2] + g_ssp[(size_t)m * 2 + 1];
    g_invrms[m] = rsqrtf(s * (1.f / (float)C_) + 1e-6f);
}

// ---------------- K5b: finalize werr/wkey ----------------
__global__ void __launch_bounds__(256)
final_kernel(const float* __restrict__ S, const float* __restrict__ Wv)
{
    __shared__ float s_mk[64], s_mbk[64], s_xbar[256];
    int bh = blockIdx.x, b = bh >> 2, h = bh & 3, tid = threadIdx.x;
    {
        float a = 0.f;
        for (int t = 0; t < 64; t++)
            a += g_xbp[((size_t)(b * 64 + t) * 4 + h) * 256 + tid];
        s_xbar[tid] = a * (1.f / (float)N_);
    }
    if (tid < 64) {
        float s = 0.f;
        for (int t = 0; t < 32; t++)
            s += g_mkp[(size_t)(b * 32 + t) * 256 + h * 64 + tid];
        s_mk[tid] = s * (1.f / (float)N_);
    } else if (tid < 128) {
        int c = tid - 64;
        float s = 0.f;
        for (int t = 0; t < 32; t++)
            s += g_mbkp[(size_t)(b * 32 + t) * 256 + h * 64 + c];
        s_mbk[c] = s * (1.f / (float)N_);
    }
    __syncthreads();
    if (tid < 64) {
        int i = tid;
        const float* wv = Wv + (size_t)(h * 64 + i) * 256;
        float mbv = 0.f;
        for (int c = 0; c < 256; c++) mbv += wv[c] * s_xbar[c];
        const float* sd = S + (size_t)bh * 4096 + (size_t)i * 64;
        float sp = 0.f;
        for (int j = 0; j < 64; j++) sp += 0.95f * sd[j] * s_mbk[j];
        g_werr[bh * 64 + i] = mbv - sp;
        g_wkey[bh * 64 + i] = s_mk[i];
    }
}

// ---------------- K5c: S_new ----------------
__global__ void __launch_bounds__(256)
snew_kernel(const float* __restrict__ S, float* __restrict__ out_s)
{
    int idx = blockIdx.x * 256 + threadIdx.x;
    int bh = idx >> 12;
    int i = (idx >> 6) & 63;
    int j = idx & 63;
    float val = S[idx] * 0.95f + g_werr[bh * 64 + i] * g_wkey[bh * 64 + j];
    out_s[idx] = fminf(fmaxf(val, -10.f), 10.f);
}

// ---------------- launcher ----------------
extern "C" void kernel_launch(void* const* d_in, const int* in_sizes, int n_in,
                              void* d_out, int out_size)
{
    const float* x    = (const float*)d_in[0];
    const float* S    = (const float*)d_in[1];
    const float* Wq   = (const float*)d_in[2];
    const float* Wk   = (const float*)d_in[3];
    const float* Wv   = (const float*)d_in[4];
    const float* Wb   = (const float*)d_in[5];
    const float* Wo   = (const float*)d_in[6];
    const float* grms = (const float*)d_in[7];
    float* out = (float*)d_out;

    static int init = 0;
    static cudaStream_t s2, s3;
    static cudaEvent_t eF, eW, eWp, eB, eQ, eC[3];
    if (!init) {
        cudaFuncSetAttribute(gemm_proj_kernel, cudaFuncAttributeMaxDynamicSharedMemorySize, 65536);
        cudaFuncSetAttribute(gemm_k_kernel, cudaFuncAttributeMaxDynamicSharedMemorySize, 65536);
        cudaFuncSetAttribute(wprime_kernel, cudaFuncAttributeMaxDynamicSharedMemorySize, 81920);
        cudaStreamCreateWithFlags(&s2, cudaStreamNonBlocking);
        cudaStreamCreateWithFlags(&s3, cudaStreamNonBlocking);
        cudaEventCreateWithFlags(&eF, cudaEventDisableTiming);
        cudaEventCreateWithFlags(&eW, cudaEventDisableTiming);
        cudaEventCreateWithFlags(&eWp, cudaEventDisableTiming);
        cudaEventCreateWithFlags(&eB, cudaEventDisableTiming);
        cudaEventCreateWithFlags(&eQ, cudaEventDisableTiming);
        for (int i = 0; i < 3; i++) cudaEventCreateWithFlags(&eC[i], cudaEventDisableTiming);
        init = 1;
    }

    const int QTR = M_ / 4;   // 16384 rows per chunk

    // --- capture fork: s2 and s3 must join capture via an event recorded on
    // the origin stream BEFORE any work is launched on them. ---
    cudaEventRecord(eF, 0);
    cudaStreamWaitEvent(s2, eF, 0);
    cudaStreamWaitEvent(s3, eF, 0);

    // parallel prologue: convw (main), beta (s2), wprime (s3)
    convw_kernel<<<512, 256>>>(Wk, Wo, grms);
    cudaEventRecord(eW, 0);
    beta_kernel<<<8192, 256, 0, s2>>>(x, Wb);
    wprime_kernel<<<64, 256, 81920, s3>>>(S, Wq);
    cudaEventRecord(eWp, s3);

    // s2: k GEMM (needs beta + Wk) -> delta-rule tail
    cudaStreamWaitEvent(s2, eW, 0);
    gemm_k_kernel<<<dim3(2, 512), 256, 65536, s2>>>(x);

    // main: proj0 quarters (need W')
    cudaStreamWaitEvent(0, eWp, 0);
    for (int c = 0; c < 4; c++) {
        gemm_proj_kernel<<<dim3(2, 128), 256, 65536>>>(0, c * QTR, x, nullptr);
        if (c < 3) cudaEventRecord(eC[c], 0);
    }

    // s2 tail (hidden under GEMMs)
    xbar_kernel<<<1024, 256, 0, s2>>>(x);
    final_kernel<<<64, 256, 0, s2>>>(S, Wv);
    if (out_size >= OUT_MAIN + OUT_S) {
        snew_kernel<<<OUT_S / 256, 256, 0, s2>>>(S, out + OUT_MAIN);
    }
    cudaEventRecord(eB, s2);

    // s3: proj1 quarters 0..2, each gated on its proj0 chunk
    for (int c = 0; c < 3; c++) {
        cudaStreamWaitEvent(s3, eC[c], 0);
        invrms_kernel<<<QTR / 256, 256, 0, s3>>>(c * QTR);
        gemm_proj_kernel<<<dim3(2, 128), 256, 65536, s3>>>(1, c * QTR, x, out);
    }
    cudaEventRecord(eQ, s3);

    // main: proj1 quarter 3
    invrms_kernel<<<QTR / 256, 256>>>(3 * QTR);
    gemm_proj_kernel<<<dim3(2, 128), 256, 65536>>>(1, 3 * QTR, x, out);

    // join
    cudaStreamWaitEvent(0, eQ, 0);
    cudaStreamWaitEvent(0, eB, 0);
}